// round 11
// baseline (speedup 1.0000x reference)
#include <cuda_runtime.h>
#include <cstdint>

// FINAL KERNEL (converged, R1-R10). Output = constant 1.0f everywhere,
// [32,128,4096] fp32 = 64 MiB. The reference's quantum-circuit ops are
// identity stubs, so probs.sum() == 1.0 per position: the output is
// independent of all inputs and the problem reduces to a 64 MiB fill.
//
// Converged findings:
//  - L2-resident write stream (DRAM ~8%; output fits in 126 MB L2).
//  - Hard ceiling: L2 write port ~6 TB/s (~51% L2 SOL), path-independent
//    (4 STG shapes + TMA bulk store all pinned at it). Floor ~= 10.8us.
//  - Grain sweep (per-CTA): 8K->11.14, 16K->11.01/11.20, 32K->11.39,
//    64K->11.58, 256K(TMA)->13.12 us ncu. Optimum = 16 KiB/CTA.
//  - 256 thr/block > 128 thr/block; wave count immaterial at this grain.
// This kernel: 4096 blocks x 256 thr x 4 unrolled STG.E.128, warp-contiguous
// 512B segments (full-line L2 writes). ~98% of the hardware write floor;
// residual harness gap (~1.6us) is graph-replay launch overhead.

__global__ __launch_bounds__(256) void fill_ones_kernel(float4* __restrict__ out) {
    const float4 v = make_float4(1.0f, 1.0f, 1.0f, 1.0f);
    // Each block owns 256*4 = 1024 consecutive float4 (16 KiB).
    float4* p = out + (size_t)blockIdx.x * 1024 + threadIdx.x;
    #pragma unroll
    for (int k = 0; k < 4; k++) {
        p[k * 256] = v;
    }
}

extern "C" void kernel_launch(void* const* d_in, const int* in_sizes, int n_in,
                              void* d_out, int out_size) {
    (void)d_in; (void)in_sizes; (void)n_in; (void)out_size;
    // 16777216 floats = 4194304 float4 = 4096 blocks * 256 thr * 4
    fill_ones_kernel<<<4096, 256>>>(reinterpret_cast<float4*>(d_out));
}